// round 3
// baseline (speedup 1.0000x reference)
#include <cuda_runtime.h>

#define BB 8
#define NN 1024
#define HH 32
#define BN (BB*NN)

// Scratch: per-node first-layer partials u[n][h] = rho*W1[0][h] + V*W1[1][h] + 0.5*b1[h]
__device__ float g_u[BN * HH];

__device__ __forceinline__ float lrelu(float v) { return fmaxf(v, 0.01f * v); }

// ---------------------------------------------------------------------------
// Kernel 1: per-node layer-1 partials.
// ---------------------------------------------------------------------------
__global__ void precompute_u(const float* __restrict__ x,
                             const float* __restrict__ Wm1,
                             const float* __restrict__ bm1) {
    int idx = blockIdx.x * blockDim.x + threadIdx.x;   // [0, BN*HH)
    int node = idx >> 5;
    int h = idx & 31;
    float rho = x[node * 2 + 0];
    float V   = x[node * 2 + 1];
    g_u[idx] = rho * Wm1[h] + V * Wm1[HH + h] + 0.5f * bm1[h];
}

// ---------------------------------------------------------------------------
// Kernel 2: fused pair-MLP + A-weighted reduction + node MLP.
// One block per (b, i). 256 threads; each thread handles 4 j values.
// Pure scalar fp32 — no inline asm, no 64-bit register pairs.
// ---------------------------------------------------------------------------
__global__ __launch_bounds__(256) void mpnn_main(
    const float* __restrict__ x,   const float* __restrict__ A,
    const float* __restrict__ Wm2, const float* __restrict__ bm2,
    const float* __restrict__ Wm3, const float* __restrict__ bm3,
    const float* __restrict__ Wx1, const float* __restrict__ bx1,
    const float* __restrict__ Wx2, const float* __restrict__ bx2,
    const float* __restrict__ Wx3, const float* __restrict__ bx3,
    float* __restrict__ out)
{
    __shared__ float4 W2s[HH * 8];     // Wm2 row-major [k][l], 1024 floats
    __shared__ float  W3s[HH];
    __shared__ float  b2s[HH];
    __shared__ float  uis[HH];
    __shared__ float  red[256];
    __shared__ float  hsh[HH];

    const int bi  = blockIdx.x;        // b*N + i
    const int i   = bi & (NN - 1);
    const int tid = threadIdx.x;

    W2s[tid] = reinterpret_cast<const float4*>(Wm2)[tid];  // 256 float4 = 1024 floats
    if (tid < HH) {
        W3s[tid] = Wm3[tid];
        b2s[tid] = bm2[tid];
        uis[tid] = g_u[bi * HH + tid];
    }
    __syncthreads();

    const float* uB   = g_u + (bi & ~(NN - 1)) * HH;  // batch base of u
    const float* Arow = A + (long)i * NN;
    const float  bm3v = bm3[0];

    float acc = 0.0f;

    #pragma unroll 1
    for (int j = tid; j < NN; j += 256) {
        // h1 = lrelu(u_i + u_j)   (b1 split half into each u)
        float h1[HH];
        const float4* up = reinterpret_cast<const float4*>(uB + j * HH);
        #pragma unroll
        for (int m = 0; m < 8; ++m) {
            float4 t = up[m];
            h1[4*m+0] = lrelu(uis[4*m+0] + t.x);
            h1[4*m+1] = lrelu(uis[4*m+1] + t.y);
            h1[4*m+2] = lrelu(uis[4*m+2] + t.z);
            h1[4*m+3] = lrelu(uis[4*m+3] + t.w);
        }

        // h2 = bm2 + W2^T h1 : 32 scalar fp32 accumulators.
        float c[HH];
        #pragma unroll
        for (int l = 0; l < HH; ++l) c[l] = b2s[l];

        #pragma unroll
        for (int k = 0; k < HH; ++k) {
            const float a = h1[k];
            const float4* w = &W2s[k * 8];
            #pragma unroll
            for (int m = 0; m < 8; ++m) {
                float4 wv = w[m];            // LDS.128 broadcast (uniform address)
                c[4*m+0] += wv.x * a;
                c[4*m+1] += wv.y * a;
                c[4*m+2] += wv.z * a;
                c[4*m+3] += wv.w * a;
            }
        }

        // me = tanh(W3 . lrelu(h2) + b3)
        float s = 0.0f;
        #pragma unroll
        for (int l = 0; l < HH; ++l) s += lrelu(c[l]) * W3s[l];

        float me = tanhf(s + bm3v);
        acc += Arow[j] * me;                 // coalesced A read
    }

    // Block reduction of A-weighted message sum.
    red[tid] = acc;
    __syncthreads();
    #pragma unroll
    for (int s2 = 128; s2 > 0; s2 >>= 1) {
        if (tid < s2) red[tid] += red[tid + s2];
        __syncthreads();
    }

    // Node MLP: x2 = (rho_i, msg_sum) -> 32 -> 32 -> 1 (warp 0, lane = hidden unit)
    if (tid < HH) {
        const float msum = red[0];
        const float rho  = x[bi * 2 + 0];
        const int   l    = tid;

        float h1b = lrelu(rho * Wx1[l] + msum * Wx1[HH + l] + bx1[l]);
        hsh[l] = h1b;
        __syncwarp();

        float h2b = bx2[l];
        #pragma unroll
        for (int k = 0; k < HH; ++k) h2b += Wx2[k * HH + l] * hsh[k];

        float v = lrelu(h2b) * Wx3[l];
        #pragma unroll
        for (int off = 16; off; off >>= 1) v += __shfl_xor_sync(0xffffffffu, v, off);

        if (l == 0) out[bi] = tanhf(v + bx3[0]);
    }
}

// ---------------------------------------------------------------------------
extern "C" void kernel_launch(void* const* d_in, const int* in_sizes, int n_in,
                              void* d_out, int out_size) {
    const float* x   = (const float*)d_in[0];
    const float* A   = (const float*)d_in[1];
    const float* Wm1 = (const float*)d_in[2];
    const float* bm1 = (const float*)d_in[3];
    const float* Wm2 = (const float*)d_in[4];
    const float* bm2 = (const float*)d_in[5];
    const float* Wm3 = (const float*)d_in[6];
    const float* bm3 = (const float*)d_in[7];
    const float* Wx1 = (const float*)d_in[8];
    const float* bx1 = (const float*)d_in[9];
    const float* Wx2 = (const float*)d_in[10];
    const float* bx2 = (const float*)d_in[11];
    const float* Wx3 = (const float*)d_in[12];
    const float* bx3 = (const float*)d_in[13];
    float* out = (float*)d_out;

    precompute_u<<<(BN * HH) / 256, 256>>>(x, Wm1, bm1);
    mpnn_main<<<BN, 256>>>(x, A, Wm2, bm2, Wm3, bm3,
                           Wx1, bx1, Wx2, bx2, Wx3, bx3, out);
}